// round 1
// baseline (speedup 1.0000x reference)
#include <cuda_runtime.h>
#include <cuda_bf16.h>
#include <cstdint>

// Problem constants (fixed by dataset)
#define BATCH 8
#define NPTS  4096   // N == M
#define DIM   256

// Scratch (device globals; no allocations allowed)
__device__ unsigned g_min_n[BATCH * NPTS];  // per (b,n): min over m  (axis=2 min)
__device__ unsigned g_min_m[BATCH * NPTS];  // per (b,m): min over n  (axis=1 min)
__device__ float    g_xx[BATCH * NPTS];
__device__ float    g_yy[BATCH * NPTS];

// Monotone float<->unsigned mapping: order-preserving for ALL floats.
__device__ __forceinline__ unsigned f2ord(float f) {
    unsigned u = __float_as_uint(f);
    return (u & 0x80000000u) ? ~u : (u ^ 0x80000000u);
}
__device__ __forceinline__ float ord2f(unsigned u) {
    u = (u & 0x80000000u) ? (u ^ 0x80000000u) : ~u;
    return __uint_as_float(u);
}

// ---------------------------------------------------------------------------
// Kernel 1: row norms for X and Y + init min arrays.
// One warp per row (256 floats = 64 float4; each lane reads 2 float4).
// grid: (NPTS*BATCH/8, 2), block: 256
// ---------------------------------------------------------------------------
__global__ void norms_init_kernel(const float* __restrict__ X,
                                  const float* __restrict__ Y) {
    int warp = (blockIdx.x * blockDim.x + threadIdx.x) >> 5;
    int lane = threadIdx.x & 31;
    const float* src = (blockIdx.y == 0) ? X : Y;
    float*    dst_n  = (blockIdx.y == 0) ? g_xx : g_yy;
    unsigned* dst_mn = (blockIdx.y == 0) ? g_min_n : g_min_m;

    const float4* row = (const float4*)(src + (size_t)warp * DIM);
    float4 a = row[lane];
    float4 b = row[lane + 32];
    float s = a.x * a.x + a.y * a.y + a.z * a.z + a.w * a.w
            + b.x * b.x + b.y * b.y + b.z * b.z + b.w * b.w;
#pragma unroll
    for (int off = 16; off > 0; off >>= 1)
        s += __shfl_xor_sync(0xFFFFFFFFu, s, off);
    if (lane == 0) {
        dst_n[warp]  = s;
        dst_mn[warp] = 0xFFFFFFFFu;  // encodes +inf-ish (max key)
    }
}

// ---------------------------------------------------------------------------
// Kernel 2: 128x128 distance tile per block, K=DIM in chunks of 32.
// 256 threads, 8x8 register micro-tile each. Epilogue: tile row/col mins.
// grid: (NPTS/128, NPTS/128, BATCH), block: 256
// ---------------------------------------------------------------------------
#define TN 128
#define TM 128
#define TK 32
#define SPAD 132   // 132*4B = 528B = 33*16B -> float4 aligned rows, banks shifted

__global__ __launch_bounds__(256, 2)
void chamfer_tile_kernel(const float* __restrict__ X,
                         const float* __restrict__ Y) {
    __shared__ __align__(16) float As[TK][SPAD];
    __shared__ __align__(16) float Bs[TK][SPAD];

    const int tid = threadIdx.x;
    const int tx  = tid & 15;       // m micro index
    const int ty  = tid >> 4;       // n micro index
    const int b   = blockIdx.z;
    const int n0  = blockIdx.y * TN;
    const int m0  = blockIdx.x * TM;

    const float* xb = X + ((size_t)b * NPTS + n0) * DIM;
    const float* yb = Y + ((size_t)b * NPTS + m0) * DIM;

    float acc[8][8];
#pragma unroll
    for (int i = 0; i < 8; ++i)
#pragma unroll
        for (int j = 0; j < 8; ++j) acc[i][j] = 0.f;

    for (int k0 = 0; k0 < DIM; k0 += TK) {
        // cooperative load: 128 rows x 32 floats = 1024 float4 per operand
#pragma unroll
        for (int t = 0; t < 4; ++t) {
            int f4id = t * 256 + tid;
            int row  = f4id >> 3;
            int kc   = (f4id & 7) * 4;
            float4 va = *(const float4*)(xb + (size_t)row * DIM + k0 + kc);
            As[kc + 0][row] = va.x; As[kc + 1][row] = va.y;
            As[kc + 2][row] = va.z; As[kc + 3][row] = va.w;
            float4 vb = *(const float4*)(yb + (size_t)row * DIM + k0 + kc);
            Bs[kc + 0][row] = vb.x; Bs[kc + 1][row] = vb.y;
            Bs[kc + 2][row] = vb.z; Bs[kc + 3][row] = vb.w;
        }
        __syncthreads();

#pragma unroll
        for (int k = 0; k < TK; ++k) {
            float ra[8], rb[8];
            float4 a0 = *(const float4*)&As[k][ty * 8];
            float4 a1 = *(const float4*)&As[k][ty * 8 + 4];
            float4 b0 = *(const float4*)&Bs[k][tx * 8];
            float4 b1 = *(const float4*)&Bs[k][tx * 8 + 4];
            ra[0] = a0.x; ra[1] = a0.y; ra[2] = a0.z; ra[3] = a0.w;
            ra[4] = a1.x; ra[5] = a1.y; ra[6] = a1.z; ra[7] = a1.w;
            rb[0] = b0.x; rb[1] = b0.y; rb[2] = b0.z; rb[3] = b0.w;
            rb[4] = b1.x; rb[5] = b1.y; rb[6] = b1.z; rb[7] = b1.w;
#pragma unroll
            for (int i = 0; i < 8; ++i)
#pragma unroll
                for (int j = 0; j < 8; ++j)
                    acc[i][j] = fmaf(ra[i], rb[j], acc[i][j]);
        }
        __syncthreads();
    }

    // Epilogue: dist = xx + yy - 2*dot; track tile row/col mins.
    float xxr[8], yyr[8];
#pragma unroll
    for (int i = 0; i < 8; ++i) xxr[i] = g_xx[b * NPTS + n0 + ty * 8 + i];
#pragma unroll
    for (int j = 0; j < 8; ++j) yyr[j] = g_yy[b * NPTS + m0 + tx * 8 + j];

    const float INF = 3.402823466e38f;
    float rmin[8], cmin[8];
#pragma unroll
    for (int i = 0; i < 8; ++i) { rmin[i] = INF; cmin[i] = INF; }
#pragma unroll
    for (int i = 0; i < 8; ++i) {
#pragma unroll
        for (int j = 0; j < 8; ++j) {
            float d = xxr[i] + yyr[j] - 2.0f * acc[i][j];
            rmin[i] = fminf(rmin[i], d);
            cmin[j] = fminf(cmin[j], d);
        }
    }

    // Reuse As storage as reduction buffer (16 x 128 floats).
    float* red = &As[0][0];

    // Column mins (min over n within tile) -> g_min_m
#pragma unroll
    for (int j = 0; j < 8; ++j) red[ty * 128 + tx * 8 + j] = cmin[j];
    __syncthreads();
    if (tid < 128) {
        float v = INF;
#pragma unroll
        for (int r = 0; r < 16; ++r) v = fminf(v, red[r * 128 + tid]);
        atomicMin(&g_min_m[b * NPTS + m0 + tid], f2ord(v));
    }
    __syncthreads();

    // Row mins (min over m within tile) -> g_min_n
#pragma unroll
    for (int i = 0; i < 8; ++i) red[tx * 128 + ty * 8 + i] = rmin[i];
    __syncthreads();
    if (tid < 128) {
        float v = INF;
#pragma unroll
        for (int r = 0; r < 16; ++r) v = fminf(v, red[r * 128 + tid]);
        atomicMin(&g_min_n[b * NPTS + n0 + tid], f2ord(v));
    }
}

// ---------------------------------------------------------------------------
// Kernel 3: sum both min arrays -> scalar (double accumulation)
// single block, 256 threads
// ---------------------------------------------------------------------------
__global__ void finalize_kernel(float* __restrict__ out) {
    __shared__ double sm[256];
    const int tid = threadIdx.x;
    const int total = BATCH * NPTS;
    double s = 0.0;
    for (int i = tid; i < total; i += 256) s += (double)ord2f(g_min_n[i]);
    for (int i = tid; i < total; i += 256) s += (double)ord2f(g_min_m[i]);
    sm[tid] = s;
    __syncthreads();
    for (int off = 128; off > 0; off >>= 1) {
        if (tid < off) sm[tid] += sm[tid + off];
        __syncthreads();
    }
    if (tid == 0) out[0] = (float)sm[0];
}

extern "C" void kernel_launch(void* const* d_in, const int* in_sizes, int n_in,
                              void* d_out, int out_size) {
    const float* gts   = (const float*)d_in[0];  // X: [B,N,D]
    const float* preds = (const float*)d_in[1];  // Y: [B,M,D]
    float* out = (float*)d_out;

    dim3 gN((BATCH * NPTS) / 8, 2);
    norms_init_kernel<<<gN, 256>>>(gts, preds);

    dim3 gT(NPTS / TM, NPTS / TN, BATCH);
    chamfer_tile_kernel<<<gT, 256>>>(gts, preds);

    finalize_kernel<<<1, 256>>>(out);
}

// round 4
// speedup vs baseline: 4.7850x; 4.7850x over previous
#include <cuda_runtime.h>
#include <cuda_bf16.h>
#include <cstdint>

#define BATCH 8
#define NPTS  4096
#define DIM   256

// tile geometry
#define TILE_N 256            // X rows per CTA (gemm M)
#define TILE_M 128            // Y rows per CTA (gemm N)
#define KCH    32             // K floats per stage
#define NSTG   8              // DIM / KCH
#define SST    36             // smem row stride (floats): bank = (4n+k)%32, conflict-free

#define A_FLOATS (TILE_N * SST)            // 9216
#define B_FLOATS (TILE_M * SST)            // 4608
#define STAGE_FLOATS (A_FLOATS + B_FLOATS) // 13824
#define STAGE_BYTES  (STAGE_FLOATS * 4)    // 55296
#define SMEM_BYTES   (3 * STAGE_BYTES)     // 165888

// ---------------- scratch globals ----------------
__device__ unsigned g_min_n[BATCH * NPTS];
__device__ unsigned g_min_m[BATCH * NPTS];
__device__ float    g_xx[BATCH * NPTS];
__device__ float    g_yy[BATCH * NPTS];

__device__ __forceinline__ unsigned f2ord(float f) {
    unsigned u = __float_as_uint(f);
    return (u & 0x80000000u) ? ~u : (u ^ 0x80000000u);
}
__device__ __forceinline__ float ord2f(unsigned u) {
    u = (u & 0x80000000u) ? (u ^ 0x80000000u) : ~u;
    return __uint_as_float(u);
}

__device__ __forceinline__ uint32_t smem_u32(const void* p) {
    uint32_t a;
    asm("{ .reg .u64 t; cvta.to.shared.u64 t, %1; cvt.u32.u64 %0, t; }" : "=r"(a) : "l"(p));
    return a;
}
__device__ __forceinline__ void cpasync16(uint32_t dst, const float* src) {
    asm volatile("cp.async.cg.shared.global [%0], [%1], 16;" :: "r"(dst), "l"(src));
}
#define CP_COMMIT() asm volatile("cp.async.commit_group;" ::: "memory")
#define CP_WAIT2()  asm volatile("cp.async.wait_group 2;" ::: "memory")

__device__ __forceinline__ void mma_tf32(float& d0, float& d1, float& d2, float& d3,
                                         uint32_t a0, uint32_t a1, uint32_t a2, uint32_t a3,
                                         uint32_t b0, uint32_t b1) {
    asm volatile(
        "mma.sync.aligned.m16n8k8.row.col.f32.tf32.tf32.f32 "
        "{%0,%1,%2,%3}, {%4,%5,%6,%7}, {%8,%9}, {%0,%1,%2,%3};"
        : "+f"(d0), "+f"(d1), "+f"(d2), "+f"(d3)
        : "r"(a0), "r"(a1), "r"(a2), "r"(a3), "r"(b0), "r"(b1));
}

// ---------------------------------------------------------------------------
// Kernel 1: row norms + min-array init (one warp per row)
// ---------------------------------------------------------------------------
__global__ void norms_init_kernel(const float* __restrict__ X,
                                  const float* __restrict__ Y) {
    int warp = (blockIdx.x * blockDim.x + threadIdx.x) >> 5;
    int lane = threadIdx.x & 31;
    const float* src = (blockIdx.y == 0) ? X : Y;
    float*    dst_n  = (blockIdx.y == 0) ? g_xx : g_yy;
    unsigned* dst_mn = (blockIdx.y == 0) ? g_min_n : g_min_m;

    const float4* row = (const float4*)(src + (size_t)warp * DIM);
    float4 a = row[lane];
    float4 b = row[lane + 32];
    float s = a.x * a.x + a.y * a.y + a.z * a.z + a.w * a.w
            + b.x * b.x + b.y * b.y + b.z * b.z + b.w * b.w;
#pragma unroll
    for (int off = 16; off > 0; off >>= 1)
        s += __shfl_xor_sync(0xFFFFFFFFu, s, off);
    if (lane == 0) {
        dst_n[warp]  = s;
        dst_mn[warp] = 0xFFFFFFFFu;
    }
}

// ---------------------------------------------------------------------------
// Kernel 2: tf32 mma.sync tiles. CTA = 256(n) x 128(m), 512 threads.
// grid: (NPTS/TILE_M, NPTS/TILE_N, BATCH)
// ---------------------------------------------------------------------------
__global__ __launch_bounds__(512, 1)
void chamfer_mma_kernel(const float* __restrict__ X,
                        const float* __restrict__ Y) {
    extern __shared__ __align__(16) char smem[];
    float* smf = (float*)smem;
    const uint32_t sb = smem_u32(smem);

    const int tid  = threadIdx.x;
    const int wid  = tid >> 5;
    const int lane = tid & 31;
    const int r4   = lane >> 2;   // 0..7
    const int c4   = lane & 3;    // 0..3
    const int wn   = wid >> 2;    // warp n-group: 64 rows
    const int wm   = wid & 3;     // warp m-group: 32 cols

    const int b  = blockIdx.z;
    const int n0 = blockIdx.y * TILE_N;
    const int m0 = blockIdx.x * TILE_M;

    const float* xb = X + ((size_t)b * NPTS + n0) * DIM;
    const float* yb = Y + ((size_t)b * NPTS + m0) * DIM;

    // ---- async load of one K-chunk stage ----
    auto load_stage = [&](int s, int buf) {
        const uint32_t base = sb + buf * STAGE_BYTES;
        const int koff = s * KCH;
        // A: 256 rows x 8 x 16B chunks = 2048
#pragma unroll
        for (int i = 0; i < 4; ++i) {
            int cid = tid + i * 512;
            int row = cid >> 3, k4 = cid & 7;
            cpasync16(base + (uint32_t)(row * SST + k4 * 4) * 4,
                      xb + (size_t)row * DIM + koff + k4 * 4);
        }
        // B: 128 rows x 8 = 1024
#pragma unroll
        for (int i = 0; i < 2; ++i) {
            int cid = tid + i * 512;
            int row = cid >> 3, k4 = cid & 7;
            cpasync16(base + (uint32_t)(A_FLOATS + row * SST + k4 * 4) * 4,
                      yb + (size_t)row * DIM + koff + k4 * 4);
        }
    };

    // prologue: 3 stages in flight
    load_stage(0, 0); CP_COMMIT();
    load_stage(1, 1); CP_COMMIT();
    load_stage(2, 2); CP_COMMIT();

    float acc[4][4][4];
#pragma unroll
    for (int fi = 0; fi < 4; ++fi)
#pragma unroll
        for (int fj = 0; fj < 4; ++fj)
#pragma unroll
            for (int q = 0; q < 4; ++q) acc[fi][fj][q] = 0.f;

    int cur = 0;
#pragma unroll 1
    for (int s = 0; s < NSTG; ++s) {
        CP_WAIT2();
        __syncthreads();

        const float* As = smf + cur * STAGE_FLOATS;
        const float* Bs = As + A_FLOATS;
        const float* abase = As + (wn * 64 + r4) * SST + c4;
        const float* bbase = Bs + (wm * 32 + r4) * SST + c4;

#pragma unroll
        for (int k8 = 0; k8 < 4; ++k8) {
            const int k0 = k8 * 8;
            uint32_t af[4][4], bf[4][2];
#pragma unroll
            for (int fi = 0; fi < 4; ++fi) {
                const float* p = abase + fi * 16 * SST;
                af[fi][0] = __float_as_uint(p[k0]);
                af[fi][1] = __float_as_uint(p[8 * SST + k0]);
                af[fi][2] = __float_as_uint(p[k0 + 4]);
                af[fi][3] = __float_as_uint(p[8 * SST + k0 + 4]);
            }
#pragma unroll
            for (int fj = 0; fj < 4; ++fj) {
                const float* p = bbase + fj * 8 * SST;
                bf[fj][0] = __float_as_uint(p[k0]);
                bf[fj][1] = __float_as_uint(p[k0 + 4]);
            }
#pragma unroll
            for (int fi = 0; fi < 4; ++fi)
#pragma unroll
                for (int fj = 0; fj < 4; ++fj)
                    mma_tf32(acc[fi][fj][0], acc[fi][fj][1], acc[fi][fj][2], acc[fi][fj][3],
                             af[fi][0], af[fi][1], af[fi][2], af[fi][3],
                             bf[fj][0], bf[fj][1]);
        }

        __syncthreads();
        if (s + 3 < NSTG) load_stage(s + 3, cur);
        CP_COMMIT();
        cur = (cur == 2) ? 0 : cur + 1;
    }

    // ---- epilogue ----
    // stage xx/yy into smem (stage buffers no longer needed)
    __syncthreads();
    float* sxx = smf;          // 256
    float* syy = smf + 256;    // 128
    if (tid < 256)      sxx[tid] = g_xx[b * NPTS + n0 + tid];
    else if (tid < 384) syy[tid - 256] = g_yy[b * NPTS + m0 + (tid - 256)];
    __syncthreads();

    const float INF = 3.402823466e38f;
    float rmin[8], cmin[8];
#pragma unroll
    for (int i = 0; i < 8; ++i) { rmin[i] = INF; cmin[i] = INF; }

    float xr[8], yc[8];
#pragma unroll
    for (int fi = 0; fi < 4; ++fi) {
        xr[fi * 2 + 0] = sxx[wn * 64 + fi * 16 + r4];
        xr[fi * 2 + 1] = sxx[wn * 64 + fi * 16 + 8 + r4];
    }
#pragma unroll
    for (int fj = 0; fj < 4; ++fj) {
        yc[fj * 2 + 0] = syy[wm * 32 + fj * 8 + 2 * c4];
        yc[fj * 2 + 1] = syy[wm * 32 + fj * 8 + 2 * c4 + 1];
    }

#pragma unroll
    for (int fi = 0; fi < 4; ++fi)
#pragma unroll
        for (int fj = 0; fj < 4; ++fj)
#pragma unroll
            for (int r = 0; r < 2; ++r)
#pragma unroll
                for (int c = 0; c < 2; ++c) {
                    float d = xr[fi * 2 + r] + yc[fj * 2 + c]
                            - 2.0f * acc[fi][fj][2 * r + c];
                    rmin[fi * 2 + r] = fminf(rmin[fi * 2 + r], d);
                    cmin[fj * 2 + c] = fminf(cmin[fj * 2 + c], d);
                }

    // row mins: reduce across quad (lanes differing in c4)
#pragma unroll
    for (int i = 0; i < 8; ++i) {
        rmin[i] = fminf(rmin[i], __shfl_xor_sync(0xFFFFFFFFu, rmin[i], 1));
        rmin[i] = fminf(rmin[i], __shfl_xor_sync(0xFFFFFFFFu, rmin[i], 2));
    }
    if (c4 == 0) {
#pragma unroll
        for (int fi = 0; fi < 4; ++fi) {
#pragma unroll
            for (int r = 0; r < 2; ++r) {
                int row = n0 + wn * 64 + fi * 16 + 8 * r + r4;
                atomicMin(&g_min_n[b * NPTS + row], f2ord(rmin[fi * 2 + r]));
            }
        }
    }

    // col mins: reduce across lanes differing in r4
#pragma unroll
    for (int i = 0; i < 8; ++i) {
        cmin[i] = fminf(cmin[i], __shfl_xor_sync(0xFFFFFFFFu, cmin[i], 4));
        cmin[i] = fminf(cmin[i], __shfl_xor_sync(0xFFFFFFFFu, cmin[i], 8));
        cmin[i] = fminf(cmin[i], __shfl_xor_sync(0xFFFFFFFFu, cmin[i], 16));
    }
    if (r4 == 0) {
#pragma unroll
        for (int fj = 0; fj < 4; ++fj) {
#pragma unroll
            for (int c = 0; c < 2; ++c) {
                int col = m0 + wm * 32 + fj * 8 + 2 * c4 + c;
                atomicMin(&g_min_m[b * NPTS + col], f2ord(cmin[fj * 2 + c]));
            }
        }
    }
}

// ---------------------------------------------------------------------------
// Kernel 3: sum mins -> scalar
// ---------------------------------------------------------------------------
__global__ void finalize_kernel(float* __restrict__ out) {
    __shared__ double sm[256];
    const int tid = threadIdx.x;
    const int total = BATCH * NPTS;
    double s = 0.0;
    for (int i = tid; i < total; i += 256) s += (double)ord2f(g_min_n[i]);
    for (int i = tid; i < total; i += 256) s += (double)ord2f(g_min_m[i]);
    sm[tid] = s;
    __syncthreads();
    for (int off = 128; off > 0; off >>= 1) {
        if (tid < off) sm[tid] += sm[tid + off];
        __syncthreads();
    }
    if (tid == 0) out[0] = (float)sm[0];
}

extern "C" void kernel_launch(void* const* d_in, const int* in_sizes, int n_in,
                              void* d_out, int out_size) {
    const float* gts   = (const float*)d_in[0];
    const float* preds = (const float*)d_in[1];
    float* out = (float*)d_out;

    static int attr_set = 0;
    if (!attr_set) {
        cudaFuncSetAttribute(chamfer_mma_kernel,
                             cudaFuncAttributeMaxDynamicSharedMemorySize, SMEM_BYTES);
        attr_set = 1;
    }

    dim3 gN((BATCH * NPTS) / 8, 2);
    norms_init_kernel<<<gN, 256>>>(gts, preds);

    dim3 gT(NPTS / TILE_M, NPTS / TILE_N, BATCH);
    chamfer_mma_kernel<<<gT, 512, SMEM_BYTES>>>(gts, preds);

    finalize_kernel<<<1, 256>>>(out);
}

// round 5
// speedup vs baseline: 7.5503x; 1.5779x over previous
#include <cuda_runtime.h>
#include <cuda_bf16.h>
#include <cuda_fp16.h>
#include <cstdint>

#define BATCH 8
#define NPTS  4096
#define DIM   256

// tile geometry
#define TILE_N 256            // X rows per CTA (gemm M)
#define TILE_M 128            // Y rows per CTA (gemm N)
#define KCH    32             // K fp16 elements per stage
#define NSTG   8              // DIM / KCH
#define NBUF   4
#define SST    40             // smem row stride in fp16: (20g+t)%32 permutation -> conflict-free

#define A_HALFS (TILE_N * SST)             // 10240
#define B_HALFS (TILE_M * SST)             // 5120
#define STAGE_HALFS (A_HALFS + B_HALFS)    // 15360
#define STAGE_BYTES (STAGE_HALFS * 2)      // 30720
#define SMEM_BYTES  (NBUF * STAGE_BYTES)   // 122880

// ---------------- scratch globals ----------------
__device__ unsigned g_min_n[BATCH * NPTS];
__device__ unsigned g_min_m[BATCH * NPTS];
__device__ float    g_xx[BATCH * NPTS];
__device__ float    g_yy[BATCH * NPTS];
__device__ __half   g_xh[BATCH * NPTS * DIM];   // 16 MB
__device__ __half   g_yh[BATCH * NPTS * DIM];   // 16 MB

__device__ __forceinline__ unsigned f2ord(float f) {
    unsigned u = __float_as_uint(f);
    return (u & 0x80000000u) ? ~u : (u ^ 0x80000000u);
}
__device__ __forceinline__ float ord2f(unsigned u) {
    u = (u & 0x80000000u) ? (u ^ 0x80000000u) : ~u;
    return __uint_as_float(u);
}

__device__ __forceinline__ uint32_t smem_u32(const void* p) {
    uint32_t a;
    asm("{ .reg .u64 t; cvta.to.shared.u64 t, %1; cvt.u32.u64 %0, t; }" : "=r"(a) : "l"(p));
    return a;
}
__device__ __forceinline__ void cpasync16(uint32_t dst, const void* src) {
    asm volatile("cp.async.cg.shared.global [%0], [%1], 16;" :: "r"(dst), "l"(src));
}
#define CP_COMMIT() asm volatile("cp.async.commit_group;" ::: "memory")
#define CP_WAIT2()  asm volatile("cp.async.wait_group 2;" ::: "memory")

__device__ __forceinline__ void mma_f16(float& d0, float& d1, float& d2, float& d3,
                                        uint32_t a0, uint32_t a1, uint32_t a2, uint32_t a3,
                                        uint32_t b0, uint32_t b1) {
    asm volatile(
        "mma.sync.aligned.m16n8k16.row.col.f32.f16.f16.f32 "
        "{%0,%1,%2,%3}, {%4,%5,%6,%7}, {%8,%9}, {%0,%1,%2,%3};"
        : "+f"(d0), "+f"(d1), "+f"(d2), "+f"(d3)
        : "r"(a0), "r"(a1), "r"(a2), "r"(a3), "r"(b0), "r"(b1));
}

// ---------------------------------------------------------------------------
// Kernel 1: row norms + min init + fp32 -> fp16 conversion (one warp per row)
// ---------------------------------------------------------------------------
__global__ void norms_init_kernel(const float* __restrict__ X,
                                  const float* __restrict__ Y) {
    int warp = (blockIdx.x * blockDim.x + threadIdx.x) >> 5;
    int lane = threadIdx.x & 31;
    const float* src = (blockIdx.y == 0) ? X : Y;
    float*    dst_n  = (blockIdx.y == 0) ? g_xx : g_yy;
    unsigned* dst_mn = (blockIdx.y == 0) ? g_min_n : g_min_m;
    __half*   dst_h  = (blockIdx.y == 0) ? g_xh : g_yh;

    const float4* row = (const float4*)(src + (size_t)warp * DIM);
    float4 a = row[lane];
    float4 b = row[lane + 32];

    __half2* hrow = (__half2*)(dst_h + (size_t)warp * DIM);
    hrow[lane * 2 + 0]      = __floats2half2_rn(a.x, a.y);
    hrow[lane * 2 + 1]      = __floats2half2_rn(a.z, a.w);
    hrow[64 + lane * 2 + 0] = __floats2half2_rn(b.x, b.y);
    hrow[64 + lane * 2 + 1] = __floats2half2_rn(b.z, b.w);

    float s = a.x * a.x + a.y * a.y + a.z * a.z + a.w * a.w
            + b.x * b.x + b.y * b.y + b.z * b.z + b.w * b.w;
#pragma unroll
    for (int off = 16; off > 0; off >>= 1)
        s += __shfl_xor_sync(0xFFFFFFFFu, s, off);
    if (lane == 0) {
        dst_n[warp]  = s;
        dst_mn[warp] = 0xFFFFFFFFu;
    }
}

// ---------------------------------------------------------------------------
// Kernel 2: fp16 mma.sync tiles. CTA = 256(n) x 128(m), 512 threads.
// grid: (NPTS/TILE_M, NPTS/TILE_N, BATCH)
// ---------------------------------------------------------------------------
__global__ __launch_bounds__(512, 1)
void chamfer_mma_kernel() {
    extern __shared__ __align__(16) char smem[];
    __half* smh = (__half*)smem;
    const uint32_t sb = smem_u32(smem);

    const int tid  = threadIdx.x;
    const int wid  = tid >> 5;
    const int lane = tid & 31;
    const int r4   = lane >> 2;   // groupID 0..7
    const int c4   = lane & 3;    // threadID-in-group 0..3
    const int wn   = wid >> 2;    // warp n-group: 64 rows
    const int wm   = wid & 3;     // warp m-group: 32 cols

    const int b  = blockIdx.z;
    const int n0 = blockIdx.y * TILE_N;
    const int m0 = blockIdx.x * TILE_M;

    const __half* xb = g_xh + ((size_t)b * NPTS + n0) * DIM;
    const __half* yb = g_yh + ((size_t)b * NPTS + m0) * DIM;

    // ---- async load of one K-chunk stage (KCH=32 fp16 per row) ----
    auto load_stage = [&](int s, int buf) {
        const uint32_t base = sb + buf * STAGE_BYTES;
        const int koff = s * KCH;
        // A: 256 rows x 4 chunks of 8 fp16 (16B) = 1024
#pragma unroll
        for (int i = 0; i < 2; ++i) {
            int cid = tid + i * 512;
            int row = cid >> 2, k8 = cid & 3;
            cpasync16(base + (uint32_t)(row * 80 + k8 * 16),
                      xb + (size_t)row * DIM + koff + k8 * 8);
        }
        // B: 128 rows x 4 = 512
        {
            int row = tid >> 2, k8 = tid & 3;
            cpasync16(base + (uint32_t)(A_HALFS * 2 + row * 80 + k8 * 16),
                      yb + (size_t)row * DIM + koff + k8 * 8);
        }
    };

    // prologue: 3 stages in flight
    load_stage(0, 0); CP_COMMIT();
    load_stage(1, 1); CP_COMMIT();
    load_stage(2, 2); CP_COMMIT();

    float acc[4][4][4];
#pragma unroll
    for (int fi = 0; fi < 4; ++fi)
#pragma unroll
        for (int fj = 0; fj < 4; ++fj)
#pragma unroll
            for (int q = 0; q < 4; ++q) acc[fi][fj][q] = 0.f;

#pragma unroll 1
    for (int s = 0; s < NSTG; ++s) {
        CP_WAIT2();
        __syncthreads();

        const __half* As = smh + (s & 3) * STAGE_HALFS;
        const __half* Bs = As + A_HALFS;
        const __half* abase = As + (wn * 64 + r4) * SST + 2 * c4;
        const __half* bbase = Bs + (wm * 32 + r4) * SST + 2 * c4;

#pragma unroll
        for (int k16 = 0; k16 < 2; ++k16) {
            const int k0 = k16 * 16;
            uint32_t af[4][4], bf[4][2];
#pragma unroll
            for (int fi = 0; fi < 4; ++fi) {
                const __half* p = abase + fi * 16 * SST + k0;
                af[fi][0] = *(const uint32_t*)(p);
                af[fi][1] = *(const uint32_t*)(p + 8 * SST);
                af[fi][2] = *(const uint32_t*)(p + 8);
                af[fi][3] = *(const uint32_t*)(p + 8 * SST + 8);
            }
#pragma unroll
            for (int fj = 0; fj < 4; ++fj) {
                const __half* p = bbase + fj * 8 * SST + k0;
                bf[fj][0] = *(const uint32_t*)(p);
                bf[fj][1] = *(const uint32_t*)(p + 8);
            }
#pragma unroll
            for (int fi = 0; fi < 4; ++fi)
#pragma unroll
                for (int fj = 0; fj < 4; ++fj)
                    mma_f16(acc[fi][fj][0], acc[fi][fj][1], acc[fi][fj][2], acc[fi][fj][3],
                            af[fi][0], af[fi][1], af[fi][2], af[fi][3],
                            bf[fj][0], bf[fj][1]);
        }

        // load into buffer (s-1)&3: safe — everyone passed top-of-loop sync
        if (s + 3 < NSTG) load_stage(s + 3, (s + 3) & 3);
        CP_COMMIT();
    }

    // ---- epilogue ----
    __syncthreads();
    float* sxx = (float*)smem;        // 256
    float* syy = (float*)smem + 256;  // 128
    if (tid < 256)      sxx[tid] = g_xx[b * NPTS + n0 + tid];
    else if (tid < 384) syy[tid - 256] = g_yy[b * NPTS + m0 + (tid - 256)];
    __syncthreads();

    const float INF = 3.402823466e38f;
    float rmin[8], cmin[8];
#pragma unroll
    for (int i = 0; i < 8; ++i) { rmin[i] = INF; cmin[i] = INF; }

    float xr[8], yc[8];
#pragma unroll
    for (int fi = 0; fi < 4; ++fi) {
        xr[fi * 2 + 0] = sxx[wn * 64 + fi * 16 + r4];
        xr[fi * 2 + 1] = sxx[wn * 64 + fi * 16 + 8 + r4];
    }
#pragma unroll
    for (int fj = 0; fj < 4; ++fj) {
        yc[fj * 2 + 0] = syy[wm * 32 + fj * 8 + 2 * c4];
        yc[fj * 2 + 1] = syy[wm * 32 + fj * 8 + 2 * c4 + 1];
    }

#pragma unroll
    for (int fi = 0; fi < 4; ++fi)
#pragma unroll
        for (int fj = 0; fj < 4; ++fj)
#pragma unroll
            for (int r = 0; r < 2; ++r)
#pragma unroll
                for (int c = 0; c < 2; ++c) {
                    float d = xr[fi * 2 + r] + yc[fj * 2 + c]
                            - 2.0f * acc[fi][fj][2 * r + c];
                    rmin[fi * 2 + r] = fminf(rmin[fi * 2 + r], d);
                    cmin[fj * 2 + c] = fminf(cmin[fj * 2 + c], d);
                }

    // row mins: reduce across quad lanes (c4)
#pragma unroll
    for (int i = 0; i < 8; ++i) {
        rmin[i] = fminf(rmin[i], __shfl_xor_sync(0xFFFFFFFFu, rmin[i], 1));
        rmin[i] = fminf(rmin[i], __shfl_xor_sync(0xFFFFFFFFu, rmin[i], 2));
    }
    if (c4 == 0) {
#pragma unroll
        for (int fi = 0; fi < 4; ++fi)
#pragma unroll
            for (int r = 0; r < 2; ++r) {
                int row = n0 + wn * 64 + fi * 16 + 8 * r + r4;
                atomicMin(&g_min_n[b * NPTS + row], f2ord(rmin[fi * 2 + r]));
            }
    }

    // col mins: reduce across r4 lanes
#pragma unroll
    for (int i = 0; i < 8; ++i) {
        cmin[i] = fminf(cmin[i], __shfl_xor_sync(0xFFFFFFFFu, cmin[i], 4));
        cmin[i] = fminf(cmin[i], __shfl_xor_sync(0xFFFFFFFFu, cmin[i], 8));
        cmin[i] = fminf(cmin[i], __shfl_xor_sync(0xFFFFFFFFu, cmin[i], 16));
    }
    if (r4 == 0) {
#pragma unroll
        for (int fj = 0; fj < 4; ++fj)
#pragma unroll
            for (int c = 0; c < 2; ++c) {
                int col = m0 + wm * 32 + fj * 8 + 2 * c4 + c;
                atomicMin(&g_min_m[b * NPTS + col], f2ord(cmin[fj * 2 + c]));
            }
    }
}

// ---------------------------------------------------------------------------
// Kernel 3: sum mins -> scalar
// ---------------------------------------------------------------------------
__global__ void finalize_kernel(float* __restrict__ out) {
    __shared__ double sm[256];
    const int tid = threadIdx.x;
    const int total = BATCH * NPTS;
    double s = 0.0;
    for (int i = tid; i < total; i += 256) s += (double)ord2f(g_min_n[i]);
    for (int i = tid; i < total; i += 256) s += (double)ord2f(g_min_m[i]);
    sm[tid] = s;
    __syncthreads();
    for (int off = 128; off > 0; off >>= 1) {
        if (tid < off) sm[tid] += sm[tid + off];
        __syncthreads();
    }
    if (tid == 0) out[0] = (float)sm[0];
}

extern "C" void kernel_launch(void* const* d_in, const int* in_sizes, int n_in,
                              void* d_out, int out_size) {
    const float* gts   = (const float*)d_in[0];
    const float* preds = (const float*)d_in[1];
    float* out = (float*)d_out;

    static int attr_set = 0;
    if (!attr_set) {
        cudaFuncSetAttribute(chamfer_mma_kernel,
                             cudaFuncAttributeMaxDynamicSharedMemorySize, SMEM_BYTES);
        attr_set = 1;
    }

    dim3 gN((BATCH * NPTS) / 8, 2);
    norms_init_kernel<<<gN, 256>>>(gts, preds);

    dim3 gT(NPTS / TILE_M, NPTS / TILE_N, BATCH);
    chamfer_mma_kernel<<<gT, 512, SMEM_BYTES>>>();

    finalize_kernel<<<1, 256>>>(out);
}

// round 7
// speedup vs baseline: 7.9231x; 1.0494x over previous
#include <cuda_runtime.h>
#include <cuda_bf16.h>
#include <cuda_fp16.h>
#include <cstdint>

#define BATCH 8
#define NPTS  4096
#define DIM   256

// tile geometry
#define TILE_N 256            // X rows per CTA (gemm M)
#define TILE_M 128            // Y rows per CTA (gemm N)
#define KCH    32             // K fp16 elements per stage
#define NSTG   8              // DIM / KCH
#define NBUF   4
#define SST    40             // smem row stride in fp16 (80B rows; ldmatrix conflict-free)

#define A_HALFS (TILE_N * SST)             // 10240
#define B_HALFS (TILE_M * SST)             // 5120
#define STAGE_HALFS (A_HALFS + B_HALFS)    // 15360
#define STAGE_BYTES (STAGE_HALFS * 2)      // 30720
#define SMEM_BYTES  (NBUF * STAGE_BYTES)   // 122880

// ---------------- scratch globals ----------------
__device__ unsigned g_min_n[BATCH * NPTS];
__device__ unsigned g_min_m[BATCH * NPTS];
__device__ float    g_xx[BATCH * NPTS];
__device__ float    g_yy[BATCH * NPTS];
__device__ __half   g_xh[BATCH * NPTS * DIM];   // 16 MB
__device__ __half   g_yh[BATCH * NPTS * DIM];   // 16 MB

__device__ __forceinline__ unsigned f2ord(float f) {
    unsigned u = __float_as_uint(f);
    return (u & 0x80000000u) ? ~u : (u ^ 0x80000000u);
}
__device__ __forceinline__ float ord2f(unsigned u) {
    u = (u & 0x80000000u) ? (u ^ 0x80000000u) : ~u;
    return __uint_as_float(u);
}

__device__ __forceinline__ uint32_t smem_u32(const void* p) {
    uint32_t a;
    asm("{ .reg .u64 t; cvta.to.shared.u64 t, %1; cvt.u32.u64 %0, t; }" : "=r"(a) : "l"(p));
    return a;
}
__device__ __forceinline__ void cpasync16(uint32_t dst, const void* src) {
    asm volatile("cp.async.cg.shared.global [%0], [%1], 16;" :: "r"(dst), "l"(src));
}
#define CP_COMMIT() asm volatile("cp.async.commit_group;" ::: "memory")
#define CP_WAIT2()  asm volatile("cp.async.wait_group 2;" ::: "memory")

#define LDSM_X4(r, a) \
    asm volatile("ldmatrix.sync.aligned.m8n8.x4.shared.b16 {%0,%1,%2,%3}, [%4];" \
        : "=r"((r)[0]), "=r"((r)[1]), "=r"((r)[2]), "=r"((r)[3]) : "r"(a))

__device__ __forceinline__ void mma_f16(float& d0, float& d1, float& d2, float& d3,
                                        uint32_t a0, uint32_t a1, uint32_t a2, uint32_t a3,
                                        uint32_t b0, uint32_t b1) {
    asm volatile(
        "mma.sync.aligned.m16n8k16.row.col.f32.f16.f16.f32 "
        "{%0,%1,%2,%3}, {%4,%5,%6,%7}, {%8,%9}, {%0,%1,%2,%3};"
        : "+f"(d0), "+f"(d1), "+f"(d2), "+f"(d3)
        : "r"(a0), "r"(a1), "r"(a2), "r"(a3), "r"(b0), "r"(b1));
}

// ---------------------------------------------------------------------------
// Kernel 1: row norms + min init + fp32 -> fp16 conversion (one warp per row)
// ---------------------------------------------------------------------------
__global__ void norms_init_kernel(const float* __restrict__ X,
                                  const float* __restrict__ Y) {
    int warp = (blockIdx.x * blockDim.x + threadIdx.x) >> 5;
    int lane = threadIdx.x & 31;
    const float* src = (blockIdx.y == 0) ? X : Y;
    float*    dst_n  = (blockIdx.y == 0) ? g_xx : g_yy;
    unsigned* dst_mn = (blockIdx.y == 0) ? g_min_n : g_min_m;
    __half*   dst_h  = (blockIdx.y == 0) ? g_xh : g_yh;

    const float4* row = (const float4*)(src + (size_t)warp * DIM);
    float4 a = row[lane];
    float4 b = row[lane + 32];

    __half2* hrow = (__half2*)(dst_h + (size_t)warp * DIM);
    hrow[lane * 2 + 0]      = __floats2half2_rn(a.x, a.y);
    hrow[lane * 2 + 1]      = __floats2half2_rn(a.z, a.w);
    hrow[64 + lane * 2 + 0] = __floats2half2_rn(b.x, b.y);
    hrow[64 + lane * 2 + 1] = __floats2half2_rn(b.z, b.w);

    float s = a.x * a.x + a.y * a.y + a.z * a.z + a.w * a.w
            + b.x * b.x + b.y * b.y + b.z * b.z + b.w * b.w;
#pragma unroll
    for (int off = 16; off > 0; off >>= 1)
        s += __shfl_xor_sync(0xFFFFFFFFu, s, off);
    if (lane == 0) {
        dst_n[warp]  = s;
        dst_mn[warp] = 0xFFFFFFFFu;
    }
}

// ---------------------------------------------------------------------------
// Kernel 2: fp16 mma.sync + ldmatrix. CTA = 256(n) x 128(m), 512 threads.
// grid: (NPTS/TILE_M, NPTS/TILE_N, BATCH)
// ---------------------------------------------------------------------------
__global__ __launch_bounds__(512, 1)
void chamfer_mma_kernel() {
    extern __shared__ __align__(16) char smem[];
    const uint32_t sb = smem_u32(smem);

    const int tid  = threadIdx.x;
    const int wid  = tid >> 5;
    const int lane = tid & 31;
    const int r4   = lane >> 2;   // 0..7
    const int c4   = lane & 3;    // 0..3
    const int wn   = wid >> 2;    // warp n-group: 64 rows
    const int wm   = wid & 3;     // warp m-group: 32 cols

    const int b  = blockIdx.z;
    const int n0 = blockIdx.y * TILE_N;
    const int m0 = blockIdx.x * TILE_M;

    const __half* xb = g_xh + ((size_t)b * NPTS + n0) * DIM;
    const __half* yb = g_yh + ((size_t)b * NPTS + m0) * DIM;

    // per-lane ldmatrix base offsets (bytes within a stage buffer)
    // A x4: matrices {rows+0..7 k0 | rows+8..15 k0 | rows k8 | rows+8 k8}
    const uint32_t a_off = (uint32_t)(((wn * 64 + (lane & 15)) * SST
                                       + ((lane >> 4) & 1) * 8) * 2);
    // B x4: {fj0 k0 | fj0 k8 | fj1 k0 | fj1 k8}; fjpair adds 16 rows
    const uint32_t b_off = (uint32_t)(A_HALFS * 2
                         + ((wm * 32 + (lane >> 4) * 8 + (lane & 7)) * SST
                            + ((lane >> 3) & 1) * 8) * 2);

    // ---- async load of one K-chunk stage (KCH=32 fp16 per row) ----
    auto load_stage = [&](int s, int buf) {
        const uint32_t base = sb + buf * STAGE_BYTES;
        const int koff = s * KCH;
#pragma unroll
        for (int i = 0; i < 2; ++i) {
            int cid = tid + i * 512;
            int row = cid >> 2, k8 = cid & 3;
            cpasync16(base + (uint32_t)(row * 80 + k8 * 16),
                      xb + (size_t)row * DIM + koff + k8 * 8);
        }
        {
            int row = tid >> 2, k8 = tid & 3;
            cpasync16(base + (uint32_t)(A_HALFS * 2 + row * 80 + k8 * 16),
                      yb + (size_t)row * DIM + koff + k8 * 8);
        }
    };

    load_stage(0, 0); CP_COMMIT();
    load_stage(1, 1); CP_COMMIT();
    load_stage(2, 2); CP_COMMIT();

    float acc[4][4][4];
#pragma unroll
    for (int fi = 0; fi < 4; ++fi)
#pragma unroll
        for (int fj = 0; fj < 4; ++fj)
#pragma unroll
            for (int q = 0; q < 4; ++q) acc[fi][fj][q] = 0.f;

#pragma unroll 1
    for (int s = 0; s < NSTG; ++s) {
        CP_WAIT2();
        __syncthreads();

        const uint32_t stage = sb + (s & 3) * STAGE_BYTES;
        const uint32_t a_base = stage + a_off;
        const uint32_t b_base = stage + b_off;

#pragma unroll
        for (int k16 = 0; k16 < 2; ++k16) {
            const uint32_t kb = k16 * 32;   // +16 halfs
            uint32_t af[4][4], bf0[4], bf1[4];
            LDSM_X4(bf0, b_base + kb);                       // bf[0][0],bf[0][1],bf[1][0],bf[1][1]
            LDSM_X4(bf1, b_base + 16 * SST * 2 + kb);        // bf[2..3]
#pragma unroll
            for (int fi = 0; fi < 4; ++fi)
                LDSM_X4(af[fi], a_base + fi * 16 * SST * 2 + kb);

#pragma unroll
            for (int fi = 0; fi < 4; ++fi) {
                mma_f16(acc[fi][0][0], acc[fi][0][1], acc[fi][0][2], acc[fi][0][3],
                        af[fi][0], af[fi][1], af[fi][2], af[fi][3], bf0[0], bf0[1]);
                mma_f16(acc[fi][1][0], acc[fi][1][1], acc[fi][1][2], acc[fi][1][3],
                        af[fi][0], af[fi][1], af[fi][2], af[fi][3], bf0[2], bf0[3]);
                mma_f16(acc[fi][2][0], acc[fi][2][1], acc[fi][2][2], acc[fi][2][3],
                        af[fi][0], af[fi][1], af[fi][2], af[fi][3], bf1[0], bf1[1]);
                mma_f16(acc[fi][3][0], acc[fi][3][1], acc[fi][3][2], acc[fi][3][3],
                        af[fi][0], af[fi][1], af[fi][2], af[fi][3], bf1[2], bf1[3]);
            }
        }

        if (s + 3 < NSTG) load_stage(s + 3, (s + 3) & 3);
        CP_COMMIT();
    }

    // ---- epilogue ----
    __syncthreads();
    float* sxx = (float*)smem;        // 256
    float* syy = (float*)smem + 256;  // 128
    if (tid < 256)      sxx[tid] = g_xx[b * NPTS + n0 + tid];
    else if (tid < 384) syy[tid - 256] = g_yy[b * NPTS + m0 + (tid - 256)];
    __syncthreads();

    const float INF = 3.402823466e38f;
    float rmin[8], cmin[8];
#pragma unroll
    for (int i = 0; i < 8; ++i) { rmin[i] = INF; cmin[i] = INF; }

    float xr[8], yc[8];
#pragma unroll
    for (int fi = 0; fi < 4; ++fi) {
        xr[fi * 2 + 0] = sxx[wn * 64 + fi * 16 + r4];
        xr[fi * 2 + 1] = sxx[wn * 64 + fi * 16 + 8 + r4];
    }
#pragma unroll
    for (int fj = 0; fj < 4; ++fj) {
        yc[fj * 2 + 0] = syy[wm * 32 + fj * 8 + 2 * c4];
        yc[fj * 2 + 1] = syy[wm * 32 + fj * 8 + 2 * c4 + 1];
    }

#pragma unroll
    for (int fi = 0; fi < 4; ++fi)
#pragma unroll
        for (int fj = 0; fj < 4; ++fj)
#pragma unroll
            for (int r = 0; r < 2; ++r)
#pragma unroll
                for (int c = 0; c < 2; ++c) {
                    float d = xr[fi * 2 + r] + yc[fj * 2 + c]
                            - 2.0f * acc[fi][fj][2 * r + c];
                    rmin[fi * 2 + r] = fminf(rmin[fi * 2 + r], d);
                    cmin[fj * 2 + c] = fminf(cmin[fj * 2 + c], d);
                }

    // row mins: reduce across quad lanes (c4)
#pragma unroll
    for (int i = 0; i < 8; ++i) {
        rmin[i] = fminf(rmin[i], __shfl_xor_sync(0xFFFFFFFFu, rmin[i], 1));
        rmin[i] = fminf(rmin[i], __shfl_xor_sync(0xFFFFFFFFu, rmin[i], 2));
    }
    if (c4 == 0) {
#pragma unroll
        for (int fi = 0; fi < 4; ++fi)
#pragma unroll
            for (int r = 0; r < 2; ++r) {
                int row = n0 + wn * 64 + fi * 16 + 8 * r + r4;
                atomicMin(&g_min_n[b * NPTS + row], f2ord(rmin[fi * 2 + r]));
            }
    }

    // col mins: reduce across r4 lanes
#pragma unroll
    for (int i = 0; i < 8; ++i) {
        cmin[i] = fminf(cmin[i], __shfl_xor_sync(0xFFFFFFFFu, cmin[i], 4));
        cmin[i] = fminf(cmin[i], __shfl_xor_sync(0xFFFFFFFFu, cmin[i], 8));
        cmin[i] = fminf(cmin[i], __shfl_xor_sync(0xFFFFFFFFu, cmin[i], 16));
    }
    if (r4 == 0) {
#pragma unroll
        for (int fj = 0; fj < 4; ++fj)
#pragma unroll
            for (int c = 0; c < 2; ++c) {
                int col = m0 + wm * 32 + fj * 8 + 2 * c4 + c;
                atomicMin(&g_min_m[b * NPTS + col], f2ord(cmin[fj * 2 + c]));
            }
    }
}

// ---------------------------------------------------------------------------
// Kernel 3: sum mins -> scalar
// ---------------------------------------------------------------------------
__global__ void finalize_kernel(float* __restrict__ out) {
    __shared__ double sm[1024];
    const int tid = threadIdx.x;
    const int total = BATCH * NPTS;
    double s = 0.0;
    for (int i = tid; i < total; i += 1024) s += (double)ord2f(g_min_n[i]);
    for (int i = tid; i < total; i += 1024) s += (double)ord2f(g_min_m[i]);
    sm[tid] = s;
    __syncthreads();
    for (int off = 512; off > 0; off >>= 1) {
        if (tid < off) sm[tid] += sm[tid + off];
        __syncthreads();
    }
    if (tid == 0) out[0] = (float)sm[0];
}

extern "C" void kernel_launch(void* const* d_in, const int* in_sizes, int n_in,
                              void* d_out, int out_size) {
    const float* gts   = (const float*)d_in[0];
    const float* preds = (const float*)d_in[1];
    float* out = (float*)d_out;

    static int attr_set = 0;
    if (!attr_set) {
        cudaFuncSetAttribute(chamfer_mma_kernel,
                             cudaFuncAttributeMaxDynamicSharedMemorySize, SMEM_BYTES);
        attr_set = 1;
    }

    dim3 gN((BATCH * NPTS) / 8, 2);
    norms_init_kernel<<<gN, 256>>>(gts, preds);

    dim3 gT(NPTS / TILE_M, NPTS / TILE_N, BATCH);
    chamfer_mma_kernel<<<gT, 512, SMEM_BYTES>>>();

    finalize_kernel<<<1, 1024>>>(out);
}